// round 2
// baseline (speedup 1.0000x reference)
#include <cuda_runtime.h>
#include <cuda_bf16.h>

#define BATCH 16
#define SEQ   2048
#define DIM   64

// Persistent scratch for M = K^T Q per batch (64x64 fp32 each).
__device__ float M_g[BATCH * DIM * DIM];

typedef unsigned long long u64;

__device__ __forceinline__ u64 pk2(float lo, float hi) {
    u64 r;
    asm("mov.b64 %0, {%1,%2};" : "=l"(r) : "f"(lo), "f"(hi));
    return r;
}
__device__ __forceinline__ void upk2(u64 v, float &lo, float &hi) {
    asm("mov.b64 {%0,%1}, %2;" : "=f"(lo), "=f"(hi) : "l"(v));
}
// packed dual-FMA: d.lo += a.lo*b.lo ; d.hi += a.hi*b.hi
__device__ __forceinline__ void fma2(u64 &d, u64 a, u64 b) {
    asm("fma.rn.f32x2 %0, %1, %2, %0;" : "+l"(d) : "l"(a), "l"(b));
}

// ---------------------------------------------------------------------------
// Kernel 0: zero the M scratch (graph replays reuse it, must re-zero).
// ---------------------------------------------------------------------------
__global__ void zero_m_kernel() {
    int i = blockIdx.x * blockDim.x + threadIdx.x;
    if (i < BATCH * DIM * DIM) M_g[i] = 0.0f;
}

// ---------------------------------------------------------------------------
// Kernel 1: M[b][d1][d2] += sum_s K[b,s,d1] * Q[b,s,d2]
// grid (16 batches, 8 s-chunks of 256 rows), 256 threads, 16KB static smem.
// Thread (ti,tj) owns a 4x4 tile of M; accumulates via packed f32x2 FMA.
// 128 blocks -> single wave on 148 SMs. Partial results combined with
// fp32 atomics into M_g (zeroed by kernel 0).
// ---------------------------------------------------------------------------
__global__ __launch_bounds__(256) void ktq_kernel(const float* __restrict__ Q,
                                                  const float* __restrict__ K) {
    __shared__ __align__(16) float Ksh[32][64];
    __shared__ __align__(16) float Qsh[32][64];

    const int b   = blockIdx.x;
    const int c   = blockIdx.y;
    const int tid = threadIdx.x;
    const int ti  = tid >> 4;    // 0..15 -> M rows 4*ti..4*ti+3
    const int tj  = tid & 15;    // 0..15 -> M cols 4*tj..4*tj+3

    const float* Kb = K + ((size_t)b * SEQ + (size_t)c * 256) * DIM;
    const float* Qb = Q + ((size_t)b * SEQ + (size_t)c * 256) * DIM;

    u64 acc[4][2];
#pragma unroll
    for (int i = 0; i < 4; i++) { acc[i][0] = 0ull; acc[i][1] = 0ull; }

    for (int sub = 0; sub < 8; sub++) {
        const float4* ks = (const float4*)(Kb + sub * 32 * DIM);
        const float4* qs = (const float4*)(Qb + sub * 32 * DIM);
        float4* Ks4 = (float4*)&Ksh[0][0];
        float4* Qs4 = (float4*)&Qsh[0][0];
        __syncthreads();   // protect previous iteration's reads
#pragma unroll
        for (int r = 0; r < 2; r++) {
            Ks4[tid + 256 * r] = ks[tid + 256 * r];
            Qs4[tid + 256 * r] = qs[tid + 256 * r];
        }
        __syncthreads();

#pragma unroll 8
        for (int s = 0; s < 32; s++) {
            float4 kv = *(const float4*)&Ksh[s][ti * 4];
            float4 qv = *(const float4*)&Qsh[s][tj * 4];
            u64 q0 = pk2(qv.x, qv.y);
            u64 q1 = pk2(qv.z, qv.w);
            float kk[4] = {kv.x, kv.y, kv.z, kv.w};
#pragma unroll
            for (int i = 0; i < 4; i++) {
                u64 kd = pk2(kk[i], kk[i]);
                fma2(acc[i][0], kd, q0);
                fma2(acc[i][1], kd, q1);
            }
        }
    }

    float* Mb = M_g + b * DIM * DIM;
#pragma unroll
    for (int i = 0; i < 4; i++) {
        float a0, a1, a2, a3;
        upk2(acc[i][0], a0, a1);
        upk2(acc[i][1], a2, a3);
        int row = ti * 4 + i;
        atomicAdd(&Mb[row * DIM + tj * 4 + 0], a0);
        atomicAdd(&Mb[row * DIM + tj * 4 + 1], a1);
        atomicAdd(&Mb[row * DIM + tj * 4 + 2], a2);
        atomicAdd(&Mb[row * DIM + tj * 4 + 3], a3);
    }
}

// ---------------------------------------------------------------------------
// Kernel 2: O[b,v,:] = sum_d' V[b,v,d'] * M[b][d'][:]
// grid (16 batches, 16 v-chunks of 128 rows), 128 threads.
// Thread (ti,tj) owns an 8x8 output tile: rows 8*ti.., cols 8*tj...
// V staged row-major in Vsh[128][65] (33KB static; pad 65 -> the per-dp
// column read across the warp's 4 row-groups is conflict-free).
// M rows read via __ldg float4 from global (16KB/batch, L1-resident,
// broadcast-ish across lanes) -- keeps static smem under 48KB.
// ---------------------------------------------------------------------------
#define ROWS2 128
__global__ __launch_bounds__(128) void vm_kernel(const float* __restrict__ V,
                                                 float* __restrict__ O) {
    __shared__ float Vsh[ROWS2][65];

    const int b   = blockIdx.x;
    const int vc  = blockIdx.y;
    const int tid = threadIdx.x;
    const int ti  = tid >> 3;   // 0..15 -> rows 8*ti..8*ti+7
    const int tj  = tid & 7;    // 0..7  -> cols 8*tj..8*tj+7

    // Stage 128 V rows (coalesced float4 loads, scalar stores into padded smem).
    const float4* Vb4 = (const float4*)(V + ((size_t)b * SEQ + (size_t)vc * ROWS2) * DIM);
#pragma unroll
    for (int r = 0; r < 16; r++) {
        int f = tid + 128 * r;          // float4 index, 2048 total
        float4 v4 = Vb4[f];
        int row = f >> 4;
        int c   = (f & 15) * 4;
        Vsh[row][c + 0] = v4.x;
        Vsh[row][c + 1] = v4.y;
        Vsh[row][c + 2] = v4.z;
        Vsh[row][c + 3] = v4.w;
    }
    __syncthreads();

    const float* Mb = M_g + b * DIM * DIM;

    u64 acc[8][4];
#pragma unroll
    for (int i = 0; i < 8; i++)
#pragma unroll
        for (int p = 0; p < 4; p++) acc[i][p] = 0ull;

#pragma unroll 4
    for (int dp = 0; dp < DIM; dp++) {
        float4 m0 = __ldg((const float4*)(Mb + dp * DIM + tj * 8));
        float4 m1 = __ldg((const float4*)(Mb + dp * DIM + tj * 8 + 4));
        u64 mm0 = pk2(m0.x, m0.y);
        u64 mm1 = pk2(m0.z, m0.w);
        u64 mm2 = pk2(m1.x, m1.y);
        u64 mm3 = pk2(m1.z, m1.w);
#pragma unroll
        for (int i = 0; i < 8; i++) {
            float vv = Vsh[ti * 8 + i][dp];
            u64 v2 = pk2(vv, vv);
            fma2(acc[i][0], v2, mm0);
            fma2(acc[i][1], v2, mm1);
            fma2(acc[i][2], v2, mm2);
            fma2(acc[i][3], v2, mm3);
        }
    }

    float* Ob = O + ((size_t)b * SEQ + (size_t)vc * ROWS2) * DIM;
#pragma unroll
    for (int i = 0; i < 8; i++) {
        float4 o0, o1;
        upk2(acc[i][0], o0.x, o0.y);
        upk2(acc[i][1], o0.z, o0.w);
        upk2(acc[i][2], o1.x, o1.y);
        upk2(acc[i][3], o1.z, o1.w);
        float* orow = Ob + (size_t)(ti * 8 + i) * DIM + tj * 8;
        *(float4*)orow       = o0;
        *(float4*)(orow + 4) = o1;
    }
}

// ---------------------------------------------------------------------------
extern "C" void kernel_launch(void* const* d_in, const int* in_sizes, int n_in,
                              void* d_out, int out_size) {
    const float* Q = (const float*)d_in[0];
    const float* K = (const float*)d_in[1];
    const float* V = (const float*)d_in[2];
    float* O = (float*)d_out;

    zero_m_kernel<<<64, 1024>>>();
    ktq_kernel<<<dim3(BATCH, 8), 256>>>(Q, K);
    vm_kernel<<<dim3(BATCH, 16), 128>>>(V, O);
}

// round 3
// speedup vs baseline: 1.0834x; 1.0834x over previous
#include <cuda_runtime.h>
#include <cuda_bf16.h>

#define BATCH  16
#define SEQ    2048
#define DIM    64
#define NCHUNK 8
#define NBLK   (BATCH * NCHUNK)   // 128 blocks: one wave on 148 SMs (barrier-safe)

// Partial K^T*Q products: [batch][chunk][64][64]. Plain-overwritten every
// replay (no zeroing needed), 2MB -> L2-resident.
__device__ float M_part[BATCH * NCHUNK * DIM * DIM];

// Grid barrier state. bar_gen is monotonically increasing across graph
// replays (never reset -> deterministic, replay-safe). bar_cnt is reset to 0
// by the last arriving block each time.
__device__ unsigned bar_cnt = 0;
__device__ volatile unsigned bar_gen = 0;

typedef unsigned long long u64;

__device__ __forceinline__ u64 pk2(float lo, float hi) {
    u64 r;
    asm("mov.b64 %0, {%1,%2};" : "=l"(r) : "f"(lo), "f"(hi));
    return r;
}
__device__ __forceinline__ void upk2(u64 v, float &lo, float &hi) {
    asm("mov.b64 {%0,%1}, %2;" : "=f"(lo), "=f"(hi) : "l"(v));
}
// packed dual-FMA: d.lo += a.lo*b.lo ; d.hi += a.hi*b.hi
__device__ __forceinline__ void fma2(u64 &d, u64 a, u64 b) {
    asm("fma.rn.f32x2 %0, %1, %2, %0;" : "+l"(d) : "l"(a), "l"(b));
}

__device__ __forceinline__ void grid_barrier() {
    __threadfence();          // make this thread's global writes visible
    __syncthreads();
    if (threadIdx.x == 0) {
        unsigned gen = bar_gen;
        unsigned arrived = atomicAdd(&bar_cnt, 1);
        if (arrived == gridDim.x - 1) {
            bar_cnt = 0;      // reset for next replay/barrier
            __threadfence();
            bar_gen = gen + 1;
        } else {
            while (bar_gen == gen) { }
        }
    }
    __syncthreads();
    __threadfence();
}

// ---------------------------------------------------------------------------
// One persistent kernel, 128 blocks x 256 threads, 42KB static smem.
//   Phase A: M_part[b][c] = K[b, c*256:(c+1)*256]^T @ Q[b, same rows]
//   (stage V tile)  -> grid barrier ->
//   Phase C: O[b, rows] = V[b, rows] @ (sum_c M_part[b][c]),  2 dim-passes
// ---------------------------------------------------------------------------
__global__ __launch_bounds__(256, 1)
void fused_attn_kernel(const float* __restrict__ Q,
                       const float* __restrict__ K,
                       const float* __restrict__ V,
                       float* __restrict__ O) {
    // Shared memory union:
    //  Phase A: Qsh  float[32][64]  (8KB)   at offset 0
    //           Kdup u64  [32][64]  (16KB)  at offset 8192
    //  Phase C: Msh  u64  [32][32]  (8KB)   at offset 0     (32 dims x 64 cols)
    //           Vsh  float[256][33] (33.8KB) at offset 8192
    __shared__ __align__(16) unsigned char smem_raw[8192 + 33792];
    float* Qsh  = (float*)smem_raw;
    u64*   Kdup = (u64*)(smem_raw + 8192);
    u64*   Msh  = (u64*)smem_raw;
    float* Vsh  = (float*)(smem_raw + 8192);

    const int blk = blockIdx.x;
    const int t   = threadIdx.x;
    const int b   = blk >> 3;    // batch 0..15
    const int c   = blk & 7;     // 256-row chunk 0..7

    // ======================= Phase A: partial K^T Q ========================
    {
        const int ti = t >> 4;   // 0..15 -> M rows 4ti..4ti+3
        const int tj = t & 15;   // 0..15 -> M cols 4tj..4tj+3

        const float* Kb = K + ((size_t)b * SEQ + (size_t)c * 256) * DIM;
        const float* Qb = Q + ((size_t)b * SEQ + (size_t)c * 256) * DIM;

        // acc[i][pj]: rows 4ti+i, col-pair {4tj+2pj, 4tj+2pj+1}
        u64 acc[4][2];
#pragma unroll
        for (int i = 0; i < 4; i++) { acc[i][0] = 0ull; acc[i][1] = 0ull; }

        for (int sub = 0; sub < 8; sub++) {
            const float4* ks = (const float4*)(Kb + sub * 32 * DIM);
            const float4* qs = (const float4*)(Qb + sub * 32 * DIM);
            __syncthreads();
#pragma unroll
            for (int r = 0; r < 2; r++) {
                int f   = t + 256 * r;       // 512 float4 = 32 rows x 16
                int row = f >> 4;
                int c4  = (f & 15) * 4;
                float4 qv = qs[f];
                *(float4*)&Qsh[row * 64 + c4] = qv;
                float4 kv = ks[f];
                ulonglong2 ka, kb2;
                ka.x  = pk2(kv.x, kv.x);  ka.y  = pk2(kv.y, kv.y);
                kb2.x = pk2(kv.z, kv.z);  kb2.y = pk2(kv.w, kv.w);
                *(ulonglong2*)&Kdup[row * 64 + c4]     = ka;
                *(ulonglong2*)&Kdup[row * 64 + c4 + 2] = kb2;
            }
            __syncthreads();

#pragma unroll 8
            for (int s = 0; s < 32; s++) {
                ulonglong2 qp = *(const ulonglong2*)&Qsh[s * 64 + 4 * tj];
                ulonglong2 k0 = *(const ulonglong2*)&Kdup[s * 64 + 4 * ti];
                ulonglong2 k1 = *(const ulonglong2*)&Kdup[s * 64 + 4 * ti + 2];
                fma2(acc[0][0], k0.x, qp.x);  fma2(acc[0][1], k0.x, qp.y);
                fma2(acc[1][0], k0.y, qp.x);  fma2(acc[1][1], k0.y, qp.y);
                fma2(acc[2][0], k1.x, qp.x);  fma2(acc[2][1], k1.x, qp.y);
                fma2(acc[3][0], k1.y, qp.x);  fma2(acc[3][1], k1.y, qp.y);
            }
        }

        // Write partial tile (vectorized: u64 col-pairs are already adjacent).
        float* mp = M_part + (size_t)blk * DIM * DIM;
#pragma unroll
        for (int i = 0; i < 4; i++) {
            float4 o;
            upk2(acc[i][0], o.x, o.y);
            upk2(acc[i][1], o.z, o.w);
            *(float4*)&mp[(4 * ti + i) * 64 + 4 * tj] = o;
        }
    }

    __syncthreads();   // everyone done reading Qsh/Kdup before Vsh overwrites

    // ===== Stage V tile for pass 0 BEFORE the barrier (hides barrier wait) ==
    const float* Vb = V + ((size_t)b * SEQ + (size_t)c * 256) * DIM;
#pragma unroll
    for (int i = 0; i < 8; i++) {
        int g   = t + 256 * i;     // 2048 float4 = 256 rows x 8
        int row = g >> 3;
        int c4  = g & 7;
        float4 v4 = ((const float4*)(Vb + (size_t)row * DIM))[c4];  // dims 0..31
        Vsh[row * 33 + c4 * 4 + 0] = v4.x;
        Vsh[row * 33 + c4 * 4 + 1] = v4.y;
        Vsh[row * 33 + c4 * 4 + 2] = v4.z;
        Vsh[row * 33 + c4 * 4 + 3] = v4.w;
    }

    grid_barrier();    // all M_part partials now visible

    // ============== Phase C: O = V @ (sum of partials), 2 passes ===========
    const int r0 = t & 127;     // this thread: rows r0 and r0+128
    const int ch = t >> 7;      // col half: cols ch*32 .. ch*32+31

    u64 accA[16], accB[16];
#pragma unroll
    for (int p = 0; p < 16; p++) { accA[p] = 0ull; accB[p] = 0ull; }

    const float* Mpb = M_part + (size_t)(b * NCHUNK) * DIM * DIM;

    for (int pass = 0; pass < 2; pass++) {
        const int dlo = pass * 32;

        if (pass == 1) {
            __syncthreads();   // done reading pass-0 tiles
            // Restage V (dims 32..63)
#pragma unroll
            for (int i = 0; i < 8; i++) {
                int g   = t + 256 * i;
                int row = g >> 3;
                int c4  = g & 7;
                float4 v4 = ((const float4*)(Vb + (size_t)row * DIM + 32))[c4];
                Vsh[row * 33 + c4 * 4 + 0] = v4.x;
                Vsh[row * 33 + c4 * 4 + 1] = v4.y;
                Vsh[row * 33 + c4 * 4 + 2] = v4.z;
                Vsh[row * 33 + c4 * 4 + 3] = v4.w;
            }
        }

        // Stage Msh for this pass: sum the 8 chunk partials (L2-resident).
        // Msh rows = dims dlo..dlo+31, each row 64 floats (32 u64).
#pragma unroll
        for (int i = 0; i < 2; i++) {
            int j   = t + 256 * i;     // 512 float4 = 32 rows x 16
            int row = j >> 4;
            int c4  = (j & 15) * 4;
            const float* src = Mpb + (size_t)(dlo + row) * 64 + c4;
            float4 s = *(const float4*)(src);
#pragma unroll
            for (int k = 1; k < NCHUNK; k++) {
                float4 v = *(const float4*)(src + (size_t)k * DIM * DIM);
                s.x += v.x; s.y += v.y; s.z += v.z; s.w += v.w;
            }
            *(float4*)((float*)Msh + (size_t)row * 64 + c4) = s;
        }
        __syncthreads();

#pragma unroll 4
        for (int dp = 0; dp < 32; dp++) {
            float v0 = Vsh[r0 * 33 + dp];
            float v1 = Vsh[(r0 + 128) * 33 + dp];
            u64 v0p = pk2(v0, v0);
            u64 v1p = pk2(v1, v1);
            const ulonglong2* mrow =
                (const ulonglong2*)(Msh + (size_t)dp * 32 + ch * 16);
#pragma unroll
            for (int p = 0; p < 8; p++) {
                ulonglong2 m2 = mrow[p];
                fma2(accA[2 * p + 0], v0p, m2.x);
                fma2(accA[2 * p + 1], v0p, m2.y);
                fma2(accB[2 * p + 0], v1p, m2.x);
                fma2(accB[2 * p + 1], v1p, m2.y);
            }
        }
    }

    // ============================ Write O ==================================
    float* Ob = O + ((size_t)b * SEQ + (size_t)c * 256) * DIM + ch * 32;
#pragma unroll
    for (int p = 0; p < 8; p++) {
        float4 oA, oB;
        upk2(accA[2 * p + 0], oA.x, oA.y);
        upk2(accA[2 * p + 1], oA.z, oA.w);
        upk2(accB[2 * p + 0], oB.x, oB.y);
        upk2(accB[2 * p + 1], oB.z, oB.w);
        *(float4*)(Ob + (size_t)r0 * DIM + 4 * p)         = oA;
        *(float4*)(Ob + (size_t)(r0 + 128) * DIM + 4 * p) = oB;
    }
}

// ---------------------------------------------------------------------------
extern "C" void kernel_launch(void* const* d_in, const int* in_sizes, int n_in,
                              void* d_out, int out_size) {
    const float* Q = (const float*)d_in[0];
    const float* K = (const float*)d_in[1];
    const float* V = (const float*)d_in[2];
    float* O = (float*)d_out;

    fused_attn_kernel<<<NBLK, 256>>>(Q, K, V, O);
}